// round 1
// baseline (speedup 1.0000x reference)
#include <cuda_runtime.h>
#include <math.h>

// ---------------------------------------------------------------------------
// VoxelConvolution: build 128x128x5x5x5 conv kernel from radial/SH weights,
// then 3D conv (pad 2) over x[1,128,48,48,48] -> out[1,128,48,48,48].
//
// Kernel storage layout: g_ker[tap][ci][o]  (tap = (a*5+b)*5+c), so the conv
// microkernel does acc[o][n] += A[ci][o] * B[ci][n] with vectorized LDS.
// Only taps with a^2+b^2+c^2 <= 6 (dist <= 2.449 <= R=2.5) are nonzero: 81/125.
// ---------------------------------------------------------------------------

__device__ float g_ker[125 * 128 * 128];  // 8 MB, [tap][ci][o]

// ---------------------------------------------------------------------------
// Builder: one block per tap. Reproduces _build_kernel exactly.
// ---------------------------------------------------------------------------
__global__ void build_kernel_k(const float* __restrict__ weight,   // [8][4096]
                               const float* __restrict__ scws,     // [32][32]
                               const float* __restrict__ scwv) {   // [32][32]
    int t = blockIdx.x;            // 0..124
    int a = t / 25;
    int b = (t / 5) % 5;
    int c = t % 5;

    __shared__ float emb_s[8];
    __shared__ float shv_s[3];
    if (threadIdx.x == 0) {
        double dx = a - 2, dy = b - 2, dz = c - 2;
        double d = sqrt(dx * dx + dy * dy + dz * dz);
        double step = 2.5 / 9.0;
        const double SMOOTH_C = 1.14136 * exp(2.0);
        for (int rb = 0; rb < 8; ++rb) {
            double val = (rb + 1) * step;
            double diff = (d - val) / step;
            double f = 0.0;
            if (fabs(diff) < 1.0) {
                double dc = diff;
                if (dc < -1.0 + 1e-6) dc = -1.0 + 1e-6;
                if (dc >  1.0 - 1e-6) dc =  1.0 - 1e-6;
                f = SMOOTH_C * exp(-1.0 / (1.0 + dc)) * exp(-1.0 / (1.0 - dc));
            }
            emb_s[rb] = (float)f;
        }
        double nn = d > 1e-12 ? d : 1e-12;
        const double SQ3 = 1.7320508075688772;
        shv_s[0] = (float)(SQ3 * dx / nn);
        shv_s[1] = (float)(SQ3 * dy / nn);
        shv_s[2] = (float)(SQ3 * dz / nn);
    }
    __syncthreads();

    const float PW0  = 0.125f;                  // sqrt(1/(2*32))
    const float PW1  = 0.21650635094610965f;    // sqrt(3/(2*32))
    const float SQ3f = 1.7320508075688772f;
    const float INV  = 0.17677669529663687f;    // 1/sqrt(32)
    const float INV_NVOX = 1.0f / 81.0f;

    float* A = g_ker + (size_t)t * 16384;       // [ci][o], 128x128

    for (int p = threadIdx.x; p < 1024; p += blockDim.x) {
        int u = p >> 5;      // input mul index
        int w = p & 31;      // output mul index
        float W[4];
#pragma unroll
        for (int cc = 0; cc < 4; ++cc) {
            float s = 0.f;
#pragma unroll
            for (int rb = 0; rb < 8; ++rb)
                s += emb_s[rb] * weight[rb * 4096 + cc * 1024 + u * 32 + w];
            W[cc] = s * INV_NVOX;
        }
        float ksv = (PW0 / SQ3f) * W[3];  // scalar-out <- vector-in (W4)
        float kvs = (PW1 / SQ3f) * W[1];  // vector-out <- scalar-in (W2)
        float kvv = (PW1 / SQ3f) * W[2];  // vector-out <- vector-in diag (W3)

        // scalar->scalar: out=w, in=u
        A[u * 128 + w] = PW0 * W[0];
        // vector-in -> scalar-out: in = 32 + u*3 + i, out = w
#pragma unroll
        for (int i = 0; i < 3; ++i)
            A[(32 + u * 3 + i) * 128 + w] = ksv * shv_s[i];
        // scalar-in -> vector-out: in = u, out = 32 + w*3 + k
#pragma unroll
        for (int k = 0; k < 3; ++k)
            A[u * 128 + 32 + w * 3 + k] = kvs * shv_s[k];
        // vector-in -> vector-out: diagonal in (k==i)
#pragma unroll
        for (int i = 0; i < 3; ++i)
#pragma unroll
            for (int k = 0; k < 3; ++k)
                A[(32 + u * 3 + i) * 128 + 32 + w * 3 + k] = (i == k) ? kvv : 0.f;

        // center self-connection (tap (2,2,2) = t 62), sc / N_VOX
        if (t == 62) {
            A[u * 128 + w] += INV * scws[u * 32 + w] * INV_NVOX;
#pragma unroll
            for (int k = 0; k < 3; ++k)
                A[(32 + u * 3 + k) * 128 + 32 + w * 3 + k] +=
                    INV * scwv[u * 32 + w] * INV_NVOX;
        }
    }
}

// ---------------------------------------------------------------------------
// Conv: block = 512 threads computes out[0..128 o][d][h0..h0+8][w0..w0+16].
// smem: A tile 64 KB ([ci][o] for current tap) + B slab 96 KB
//       ([ci][8 rows][24 w], input w = w0 + wi - 4) => 160 KB dynamic.
// Microtile per thread: 8 o x 4 w, all LDS.128.
// ---------------------------------------------------------------------------
__global__ void __launch_bounds__(512) conv_k(const float* __restrict__ x,
                                              float* __restrict__ out) {
    extern __shared__ float smem[];
    float* As = smem;              // 16384 floats: [ci][128 o]
    float* Bs = smem + 16384;      // 24576 floats: [ci][8][24]

    const int tid = threadIdx.x;
    const int d   = blockIdx.z;        // 0..47
    const int h0  = blockIdx.y * 8;    // 0..40
    const int w0  = blockIdx.x * 16;   // 0,16,32

    const int to     = tid & 15;       // 16 o-groups
    const int tn     = tid >> 4;       // 0..31 n-groups
    const int o_base = to * 8;
    const int r_out  = tn >> 2;        // output row within tile, 0..7
    const int wbase  = (tn & 3) * 4;   // 0,4,8,12 (16B aligned)

    float acc[8][4];
#pragma unroll
    for (int o = 0; o < 8; ++o)
#pragma unroll
        for (int j = 0; j < 4; ++j) acc[o][j] = 0.f;

    for (int a = 0; a < 5; ++a) {
        const int dd = d + a - 2;
        if (dd < 0 || dd >= 48) continue;          // zero-padded slab: all-zero
        const int da2 = (a - 2) * (a - 2);
        for (int b = 0; b < 5; ++b) {
            const int db2 = (b - 2) * (b - 2);
            if (da2 + db2 > 6) continue;           // no valid tap in this (a,b)

            __syncthreads();                       // prior compute done (Bs reuse)
            // Load B slab: Bs[ci][rr][wi] = x[ci][dd][h0+rr+b-2][w0+wi-4]
            for (int e = tid; e < 128 * 8 * 24; e += 512) {
                int wi = e % 24;
                int rr = (e / 24) & 7;
                int ci = e / 192;
                int hh = h0 + rr + b - 2;
                int ww = w0 + wi - 4;
                float v = 0.f;
                if ((unsigned)hh < 48u && (unsigned)ww < 48u)
                    v = x[((ci * 48 + dd) * 48 + hh) * 48 + ww];
                Bs[e] = v;
            }
            __syncthreads();

#pragma unroll
            for (int c = 0; c < 5; ++c) {
                if (da2 + db2 + (c - 2) * (c - 2) > 6) continue;  // zero tap
                __syncthreads();                   // prior compute done (As reuse)
                // Load A tile: 64 KB [ci][o]
                {
                    const float4* gk = reinterpret_cast<const float4*>(g_ker)
                                     + (size_t)((a * 5 + b) * 5 + c) * 4096;
                    float4* As4 = reinterpret_cast<float4*>(As);
#pragma unroll
                    for (int k = 0; k < 8; ++k)
                        As4[tid + k * 512] = gk[tid + k * 512];
                }
                __syncthreads();

                const float* Arow = As + o_base;
                const float* Brow = Bs + r_out * 24 + wbase;
#pragma unroll 2
                for (int ci = 0; ci < 128; ++ci) {
                    float4 a0 = *reinterpret_cast<const float4*>(Arow + ci * 128);
                    float4 a1 = *reinterpret_cast<const float4*>(Arow + ci * 128 + 4);
                    float4 b0 = *reinterpret_cast<const float4*>(Brow + ci * 192);
                    float4 b1 = *reinterpret_cast<const float4*>(Brow + ci * 192 + 4);
                    float4 b2 = *reinterpret_cast<const float4*>(Brow + ci * 192 + 8);
                    float av[8] = {a0.x, a0.y, a0.z, a0.w, a1.x, a1.y, a1.z, a1.w};
                    float bw[12] = {b0.x, b0.y, b0.z, b0.w,
                                    b1.x, b1.y, b1.z, b1.w,
                                    b2.x, b2.y, b2.z, b2.w};
                    // needed input w index (local) = j + c + 2  (static after unroll)
#pragma unroll
                    for (int j = 0; j < 4; ++j) {
                        float xv = bw[j + c + 2];
#pragma unroll
                        for (int o = 0; o < 8; ++o)
                            acc[o][j] = fmaf(av[o], xv, acc[o][j]);
                    }
                }
            }
        }
    }

    // Write C tile: out[o][d][h][w], 4 consecutive w per thread.
    const int h = h0 + r_out;
#pragma unroll
    for (int o = 0; o < 8; ++o) {
        float4 v = make_float4(acc[o][0], acc[o][1], acc[o][2], acc[o][3]);
        *reinterpret_cast<float4*>(
            out + (((size_t)(o_base + o) * 48 + d) * 48 + h) * 48 + w0 + wbase) = v;
    }
}

// ---------------------------------------------------------------------------
// Launch
// ---------------------------------------------------------------------------
extern "C" void kernel_launch(void* const* d_in, const int* in_sizes, int n_in,
                              void* d_out, int out_size) {
    const float* x    = (const float*)d_in[0];  // [1,128,48,48,48]
    const float* wt   = (const float*)d_in[1];  // [8,4096]
    const float* scws = (const float*)d_in[2];  // [32,32]
    const float* scwv = (const float*)d_in[3];  // [32,32]
    float* out = (float*)d_out;                 // [1,128,48,48,48]

    build_kernel_k<<<125, 256>>>(wt, scws, scwv);

    const int smem_bytes = (16384 + 24576) * 4;  // 160 KB
    cudaFuncSetAttribute(conv_k, cudaFuncAttributeMaxDynamicSharedMemorySize,
                         smem_bytes);
    dim3 grid(3, 6, 48);   // w tiles x h tiles x d
    conv_k<<<grid, 512, smem_bytes>>>(x, out);
}

// round 3
// speedup vs baseline: 3.7847x; 3.7847x over previous
#include <cuda_runtime.h>
#include <math.h>
#include <stdint.h>

// ===========================================================================
// VoxelConvolution via warp-level mma.sync TF32 implicit GEMM (compute_100-safe).
//   pad_k  : x -> xp (zero-padded +2/side, TF32 rounded)
//   build_k: weights -> g_ker[tap][o][perm(ci)]  (TF32 rounded, k-permuted)
//   conv_k : CTA tile M=128 x N=128 (8h x 16w); per (a,b) plane stage B slab
//            once (shared across c), per tap stage A, 16 k8-steps of mma.sync.
// ===========================================================================

#define PADW 52
__device__ float xp[128 * PADW * PADW * PADW];   // 72 MB padded TF32 input
__device__ float g_ker[125 * 128 * 128];         // 8 MB [tap][o][perm(ci)]

__device__ __forceinline__ float to_tf32(float x) {
    uint32_t r;
    asm("cvt.rna.tf32.f32 %0, %1;" : "=r"(r) : "f"(x));
    return __uint_as_float(r);
}
// k-permutation: within each 8-block, j -> (j&3)*2 + (j>>2), so the mma
// fragment pairs (k, k+4) land on adjacent storage columns (LDS.64-able).
__device__ __forceinline__ int kperm(int ci) {
    return (ci & ~7) | ((ci & 3) << 1) | ((ci >> 2) & 1);
}

__device__ __forceinline__ void mma8(float* c, const uint32_t* a, const uint32_t* b) {
    asm volatile(
        "mma.sync.aligned.m16n8k8.row.col.f32.tf32.tf32.f32 "
        "{%0,%1,%2,%3}, {%4,%5,%6,%7}, {%8,%9}, {%0,%1,%2,%3};"
        : "+f"(c[0]), "+f"(c[1]), "+f"(c[2]), "+f"(c[3])
        : "r"(a[0]), "r"(a[1]), "r"(a[2]), "r"(a[3]), "r"(b[0]), "r"(b[1]));
}

// ---------------------------------------------------------------------------
__global__ void pad_k(const float* __restrict__ x) {
    int idx = blockIdx.x * 512 + threadIdx.x;
    const int NP = 128 * PADW * PADW * PADW;
    if (idx >= NP) return;
    int wz = idx % PADW;
    int t = idx / PADW;
    int hz = t % PADW; t /= PADW;
    int dz = t % PADW;
    int ci = t / PADW;
    float v = 0.f;
    if (wz >= 2 && wz < 50 && hz >= 2 && hz < 50 && dz >= 2 && dz < 50)
        v = to_tf32(x[(((size_t)ci * 48 + dz - 2) * 48 + hz - 2) * 48 + wz - 2]);
    xp[idx] = v;
}

// ---------------------------------------------------------------------------
__global__ void build_k(const float* __restrict__ weight,   // [8][4096]
                        const float* __restrict__ scws,     // [32][32]
                        const float* __restrict__ scwv) {   // [32][32]
    int t = blockIdx.x;            // 0..124
    int a = t / 25, b = (t / 5) % 5, c = t % 5;

    __shared__ float emb_s[8];
    __shared__ float shv_s[3];
    if (threadIdx.x == 0) {
        double dx = a - 2, dy = b - 2, dz = c - 2;
        double d = sqrt(dx * dx + dy * dy + dz * dz);
        double step = 2.5 / 9.0;
        const double SMOOTH_C = 1.14136 * exp(2.0);
        for (int rb = 0; rb < 8; ++rb) {
            double val = (rb + 1) * step;
            double diff = (d - val) / step;
            double f = 0.0;
            if (fabs(diff) < 1.0) {
                double dc = diff;
                if (dc < -1.0 + 1e-6) dc = -1.0 + 1e-6;
                if (dc >  1.0 - 1e-6) dc =  1.0 - 1e-6;
                f = SMOOTH_C * exp(-1.0 / (1.0 + dc)) * exp(-1.0 / (1.0 - dc));
            }
            emb_s[rb] = (float)f;
        }
        double nn = d > 1e-12 ? d : 1e-12;
        const double SQ3 = 1.7320508075688772;
        shv_s[0] = (float)(SQ3 * dx / nn);
        shv_s[1] = (float)(SQ3 * dy / nn);
        shv_s[2] = (float)(SQ3 * dz / nn);
    }
    __syncthreads();

    const float PW0  = 0.125f;
    const float PW1  = 0.21650635094610965f;
    const float SQ3f = 1.7320508075688772f;
    const float INV  = 0.17677669529663687f;
    const float INV_NVOX = 1.0f / 81.0f;

    float* A = g_ker + (size_t)t * 16384;   // [o][perm(ci)]

    for (int p = threadIdx.x; p < 1024; p += blockDim.x) {
        int u  = p >> 5;   // input mul
        int wm = p & 31;   // output mul
        float W[4];
#pragma unroll
        for (int cc = 0; cc < 4; ++cc) {
            float s = 0.f;
#pragma unroll
            for (int rb = 0; rb < 8; ++rb)
                s += emb_s[rb] * weight[rb * 4096 + cc * 1024 + u * 32 + wm];
            W[cc] = s * INV_NVOX;
        }
        float ksv = (PW0 / SQ3f) * W[3];
        float kvs = (PW1 / SQ3f) * W[1];
        float kvv = (PW1 / SQ3f) * W[2];

        // scalar->scalar (o=wm, ci=u) + center self-connection
        {
            float v = PW0 * W[0];
            if (t == 62) v += INV * scws[u * 32 + wm] * INV_NVOX;
            A[wm * 128 + kperm(u)] = to_tf32(v);
        }
        // vector-in -> scalar-out
#pragma unroll
        for (int i = 0; i < 3; ++i)
            A[wm * 128 + kperm(32 + u * 3 + i)] = to_tf32(ksv * shv_s[i]);
        // scalar-in -> vector-out
#pragma unroll
        for (int k = 0; k < 3; ++k)
            A[(32 + wm * 3 + k) * 128 + kperm(u)] = to_tf32(kvs * shv_s[k]);
        // vector-in -> vector-out (diag)
#pragma unroll
        for (int i = 0; i < 3; ++i)
#pragma unroll
            for (int k = 0; k < 3; ++k) {
                float v = (i == k) ? kvv : 0.f;
                if (t == 62 && i == k) v += INV * scwv[u * 32 + wm] * INV_NVOX;
                A[(32 + wm * 3 + k) * 128 + kperm(32 + u * 3 + i)] = to_tf32(v);
            }
    }
}

// ---------------------------------------------------------------------------
// conv_k: 256 threads, 8 warps (2 M-halves x 4 N-blocks of 32).
// SMEM: As[128][136] (69,632 B) + Bs[192 spat][138-stride] (105,984 B).
// ---------------------------------------------------------------------------
#define AS_STRIDE 136
#define BS_STRIDE 138
#define AS_FLOATS (128 * AS_STRIDE)

__global__ void __launch_bounds__(256) conv_k(float* __restrict__ out) {
    extern __shared__ float sm[];
    float* As = sm;                      // [o][col], stride 136
    float* Bs = sm + AS_FLOATS;          // [spat 8x24][col], stride 138

    const int tid  = threadIdx.x;
    const int lane = tid & 31;
    const int g    = lane >> 2;          // groupID
    const int t4   = lane & 3;           // threadID in group
    const int warp = tid >> 5;
    const int mw   = warp & 1;           // M half (64)
    const int nw   = warp >> 1;          // N block (32)
    const int w0   = blockIdx.x * 16;
    const int h0   = blockIdx.y * 8;
    const int d    = blockIdx.z;

    float acc[4][4][4];
#pragma unroll
    for (int i = 0; i < 4; ++i)
#pragma unroll
        for (int j = 0; j < 4; ++j)
#pragma unroll
            for (int q = 0; q < 4; ++q) acc[i][j][q] = 0.f;

    int spatj[4];
#pragma unroll
    for (int j = 0; j < 4; ++j) {
        int nl = j * 8 + g;                              // B frag n (col=groupID)
        spatj[j] = (nw * 2 + (nl >> 4)) * 24 + (nl & 15);
    }

    for (int a = 0; a < 5; ++a) {
        const int dz  = d + a;
        const int da2 = (a - 2) * (a - 2);
        for (int b = 0; b < 5; ++b) {
            const int s2 = da2 + (b - 2) * (b - 2);
            if (s2 > 5) continue;                        // no valid tap in plane
            __syncthreads();                             // Bs free (prev mma done)
            // stage B slab transposed: Bs[(rr*24+wl)][perm(ci)], wl in [0,20)
            {
                const int hz = h0 + b;
#pragma unroll 4
                for (int it = 0; it < 80; ++it) {
                    int idx = it * 256 + tid;
                    int wl = idx % 20;
                    int t2 = idx / 20;
                    int rr = t2 & 7;
                    int ci = t2 >> 3;
                    Bs[(rr * 24 + wl) * BS_STRIDE + kperm(ci)] =
                        xp[(((size_t)ci * PADW + dz) * PADW + hz + rr) * PADW + w0 + wl];
                }
            }
            const int clo = (s2 >= 4) ? 1 : 0;
            const int chi = (s2 >= 4) ? 3 : 4;
            for (int c = clo; c <= chi; ++c) {
                __syncthreads();                         // As free + Bs visible
                // stage A: straight 64KB copy (already permuted/tf32)
                {
                    const float4* g4 = (const float4*)g_ker
                                     + (size_t)((a * 5 + b) * 5 + c) * 4096;
                    float4* A4 = (float4*)As;            // row stride = 34 float4
#pragma unroll
                    for (int i2 = 0; i2 < 16; ++i2) {
                        int idx = i2 * 256 + tid;
                        A4[(idx >> 5) * 34 + (idx & 31)] = g4[idx];
                    }
                }
                __syncthreads();

                const float* Ab = As + (mw * 64 + g) * AS_STRIDE + 2 * t4;
                const float* Bc = Bs + c * BS_STRIDE + 2 * t4;
#pragma unroll 4
                for (int kb = 0; kb < 16; ++kb) {
                    uint32_t af[4][4];
#pragma unroll
                    for (int i = 0; i < 4; ++i) {
                        float2 lo = *(const float2*)(Ab + (i * 16) * AS_STRIDE + kb * 8);
                        float2 hi = *(const float2*)(Ab + (i * 16 + 8) * AS_STRIDE + kb * 8);
                        af[i][0] = __float_as_uint(lo.x);
                        af[i][1] = __float_as_uint(hi.x);
                        af[i][2] = __float_as_uint(lo.y);
                        af[i][3] = __float_as_uint(hi.y);
                    }
                    uint32_t bf[4][2];
#pragma unroll
                    for (int j = 0; j < 4; ++j) {
                        float2 v = *(const float2*)(Bc + spatj[j] * BS_STRIDE + kb * 8);
                        bf[j][0] = __float_as_uint(v.x);
                        bf[j][1] = __float_as_uint(v.y);
                    }
#pragma unroll
                    for (int i = 0; i < 4; ++i)
#pragma unroll
                        for (int j = 0; j < 4; ++j)
                            mma8(acc[i][j], af[i], bf[j]);
                }
            }
        }
    }

    // epilogue: C frag (row=g/g+8, col=2*t4, 2*t4+1) -> float2 stores
#pragma unroll
    for (int i = 0; i < 4; ++i) {
        const int o = mw * 64 + i * 16 + g;
#pragma unroll
        for (int j = 0; j < 4; ++j) {
            const int nl = nw * 32 + j * 8 + 2 * t4;
            const int hh = h0 + (nl >> 4);
            const int ww = w0 + (nl & 15);
            float2 v0 = make_float2(acc[i][j][0], acc[i][j][1]);
            float2 v1 = make_float2(acc[i][j][2], acc[i][j][3]);
            *(float2*)(out + (((size_t)o * 48 + d) * 48 + hh) * 48 + ww) = v0;
            *(float2*)(out + (((size_t)(o + 8) * 48 + d) * 48 + hh) * 48 + ww) = v1;
        }
    }
}

// ---------------------------------------------------------------------------
extern "C" void kernel_launch(void* const* d_in, const int* in_sizes, int n_in,
                              void* d_out, int out_size) {
    const float* x    = (const float*)d_in[0];
    const float* wt   = (const float*)d_in[1];
    const float* scws = (const float*)d_in[2];
    const float* scwv = (const float*)d_in[3];
    float* out = (float*)d_out;

    const int NP = 128 * PADW * PADW * PADW;
    pad_k<<<(NP + 511) / 512, 512>>>(x);
    build_k<<<125, 256>>>(wt, scws, scwv);

    const int smem_bytes = (AS_FLOATS + 192 * BS_STRIDE) * 4;   // 175,616 B
    cudaFuncSetAttribute(conv_k, cudaFuncAttributeMaxDynamicSharedMemorySize,
                         smem_bytes);
    dim3 grid(3, 6, 48);   // w-tiles x h-tiles x d
    conv_k<<<grid, 256, smem_bytes>>>(out);
}

// round 5
// speedup vs baseline: 4.8362x; 1.2778x over previous
#include <cuda_runtime.h>
#include <math.h>
#include <stdint.h>

// ===========================================================================
// VoxelConvolution via mma.sync TF32 implicit GEMM, A pre-fragmented in global.
//   pad_k   : x -> xp (zero-padded +2/side, TF32 rounded), float4 vectorized
//   build_k : weights -> g_frag[tap][kb][mt][lane][4]  (mma fragment order)
//   conv_k  : CTA tile M=128 x N=192 (8h x 24w); B slab in smem per (a,b)
//             plane (shared across c taps, cp.async staged); A via LDG.128
//             fragments cached in L1. No per-tap syncs.
// ===========================================================================

#define PADW 52
__device__ float xp[128 * PADW * PADW * PADW];   // 72 MB padded TF32 input
__device__ float g_frag[125 * 128 * 128];        // 8 MB A fragments

__device__ __forceinline__ float to_tf32(float x) {
    uint32_t r;
    asm("cvt.rna.tf32.f32 %0, %1;" : "=r"(r) : "f"(x));
    return __uint_as_float(r);
}
// B k-permutation: pairs (k, k+4) adjacent -> LDS.64 loads
__device__ __forceinline__ int kperm(int ci) {
    return (ci & ~7) | ((ci & 3) << 1) | ((ci >> 2) & 1);
}
// A fragment offset within a tap block (16384 floats):
// [kb 16][mt 8][lane 32][q 4];  lane=(g=o&7)*4+(t4=ci&3);  q=((ci>>2)&1)*2+((o>>3)&1)
__device__ __forceinline__ int frag_off(int o, int ci) {
    int kb = ci >> 3, t4 = ci & 3, qk = (ci >> 2) & 1;
    int mt = o >> 4, g = o & 7, qr = (o >> 3) & 1;
    return (((kb * 8 + mt) * 32) + (g * 4 + t4)) * 4 + (qk * 2 + qr);
}

__device__ __forceinline__ void mma8(float* c, const uint32_t* a, const uint32_t* b) {
    asm volatile(
        "mma.sync.aligned.m16n8k8.row.col.f32.tf32.tf32.f32 "
        "{%0,%1,%2,%3}, {%4,%5,%6,%7}, {%8,%9}, {%0,%1,%2,%3};"
        : "+f"(c[0]), "+f"(c[1]), "+f"(c[2]), "+f"(c[3])
        : "r"(a[0]), "r"(a[1]), "r"(a[2]), "r"(a[3]), "r"(b[0]), "r"(b[1]));
}

__device__ __forceinline__ uint32_t smem_u32(const void* p) {
    uint32_t a;
    asm("{ .reg .u64 t; cvta.to.shared.u64 t, %1; cvt.u32.u64 %0, t; }" : "=r"(a) : "l"(p));
    return a;
}
__device__ __forceinline__ void cpa4(uint32_t dst, const float* src) {
    asm volatile("cp.async.ca.shared.global [%0], [%1], 4;" :: "r"(dst), "l"(src) : "memory");
}

// ---------------------------------------------------------------------------
__global__ void pad_k(const float* __restrict__ x) {
    int idx = blockIdx.x * 256 + threadIdx.x;
    const int N4 = 128 * PADW * PADW * 13;
    if (idx >= N4) return;
    int w4 = (idx % 13) * 4;
    int t = idx / 13;
    int hz = t % PADW; t /= PADW;
    int dz = t % PADW;
    int ci = t / PADW;
    float vv[4] = {0.f, 0.f, 0.f, 0.f};
    if (hz >= 2 && hz < 50 && dz >= 2 && dz < 50) {
        const float* row = x + (((size_t)ci * 48 + dz - 2) * 48 + hz - 2) * 48;
#pragma unroll
        for (int q = 0; q < 4; ++q) {
            int wz = w4 + q;
            if (wz >= 2 && wz < 50) vv[q] = to_tf32(row[wz - 2]);
        }
    }
    ((float4*)xp)[idx] = make_float4(vv[0], vv[1], vv[2], vv[3]);
}

// ---------------------------------------------------------------------------
__global__ void build_k(const float* __restrict__ weight,   // [8][4096]
                        const float* __restrict__ scws,     // [32][32]
                        const float* __restrict__ scwv) {   // [32][32]
    int t = blockIdx.x;            // 0..124
    int a = t / 25, b = (t / 5) % 5, c = t % 5;

    __shared__ float emb_s[8];
    __shared__ float shv_s[3];
    if (threadIdx.x == 0) {
        double dx = a - 2, dy = b - 2, dz = c - 2;
        double d = sqrt(dx * dx + dy * dy + dz * dz);
        double step = 2.5 / 9.0;
        const double SMOOTH_C = 1.14136 * exp(2.0);
        for (int rb = 0; rb < 8; ++rb) {
            double val = (rb + 1) * step;
            double diff = (d - val) / step;
            double f = 0.0;
            if (fabs(diff) < 1.0) {
                double dc = diff;
                if (dc < -1.0 + 1e-6) dc = -1.0 + 1e-6;
                if (dc >  1.0 - 1e-6) dc =  1.0 - 1e-6;
                f = SMOOTH_C * exp(-1.0 / (1.0 + dc)) * exp(-1.0 / (1.0 - dc));
            }
            emb_s[rb] = (float)f;
        }
        double nn = d > 1e-12 ? d : 1e-12;
        const double SQ3 = 1.7320508075688772;
        shv_s[0] = (float)(SQ3 * dx / nn);
        shv_s[1] = (float)(SQ3 * dy / nn);
        shv_s[2] = (float)(SQ3 * dz / nn);
    }
    __syncthreads();

    const float PW0  = 0.125f;
    const float PW1  = 0.21650635094610965f;
    const float SQ3f = 1.7320508075688772f;
    const float INV  = 0.17677669529663687f;
    const float INV_NVOX = 1.0f / 81.0f;

    float* A = g_frag + (size_t)t * 16384;

    for (int p = threadIdx.x; p < 1024; p += blockDim.x) {
        int u  = p >> 5;   // input mul
        int wm = p & 31;   // output mul
        float W[4];
#pragma unroll
        for (int cc = 0; cc < 4; ++cc) {
            float s = 0.f;
#pragma unroll
            for (int rb = 0; rb < 8; ++rb)
                s += emb_s[rb] * weight[rb * 4096 + cc * 1024 + u * 32 + wm];
            W[cc] = s * INV_NVOX;
        }
        float ksv = (PW0 / SQ3f) * W[3];
        float kvs = (PW1 / SQ3f) * W[1];
        float kvv = (PW1 / SQ3f) * W[2];

        {   // scalar->scalar (o=wm, ci=u) + center self-connection
            float v = PW0 * W[0];
            if (t == 62) v += INV * scws[u * 32 + wm] * INV_NVOX;
            A[frag_off(wm, u)] = to_tf32(v);
        }
#pragma unroll
        for (int i = 0; i < 3; ++i)       // vector-in -> scalar-out
            A[frag_off(wm, 32 + u * 3 + i)] = to_tf32(ksv * shv_s[i]);
#pragma unroll
        for (int k = 0; k < 3; ++k)       // scalar-in -> vector-out
            A[frag_off(32 + wm * 3 + k, u)] = to_tf32(kvs * shv_s[k]);
#pragma unroll
        for (int i = 0; i < 3; ++i)       // vector-in -> vector-out (diag)
#pragma unroll
            for (int k = 0; k < 3; ++k) {
                float v = (i == k) ? kvv : 0.f;
                if (t == 62 && i == k) v += INV * scwv[u * 32 + wm] * INV_NVOX;
                A[frag_off(32 + wm * 3 + k, 32 + u * 3 + i)] = to_tf32(v);
            }
    }
}

// ---------------------------------------------------------------------------
// conv_k: 384 threads (12 warps = 2 mhalf x 6 nblock), tile 128o x (8h x 24w).
// SMEM: B slab only: [224 spat rows][stride 138]  (123,648 B).
// ---------------------------------------------------------------------------
#define BS_STRIDE 138
#define BS_FLOATS (224 * BS_STRIDE)

__global__ void __launch_bounds__(384, 1) conv_k(float* __restrict__ out) {
    extern __shared__ float Bs[];
    const uint32_t bs_base = smem_u32(Bs);

    const int tid  = threadIdx.x;
    const int lane = tid & 31;
    const int g    = lane >> 2;
    const int t4   = lane & 3;
    const int warp = tid >> 5;
    const int mw   = warp & 1;          // m half (64)
    const int nw   = warp >> 1;         // n block (32), 0..5
    const int w0   = blockIdx.x * 24;
    const int h0   = blockIdx.y * 8;
    const int d    = blockIdx.z;

    float acc[4][4][4];
#pragma unroll
    for (int i = 0; i < 4; ++i)
#pragma unroll
        for (int j = 0; j < 4; ++j)
#pragma unroll
            for (int q = 0; q < 4; ++q) acc[i][j][q] = 0.f;

    int spatj[4];
#pragma unroll
    for (int j = 0; j < 4; ++j) {
        int nl = nw * 32 + j * 8 + g;   // B frag col = groupID
        spatj[j] = (nl / 24) * 28 + (nl % 24);
    }

    for (int a = 0; a < 5; ++a) {
        const int dz  = d + a;
        const int da2 = (a - 2) * (a - 2);
        for (int b = 0; b < 5; ++b) {
            const int s2 = da2 + (b - 2) * (b - 2);
            if (s2 > 5) continue;                    // no valid tap in plane
            __syncthreads();                         // Bs free (prev mma done)
            {   // stage B slab: Bs[rr*28+wl][kperm(ci)] via cp.async 4B
                const int hz = h0 + b;
                for (int e = tid; e < 28672; e += 384) {
                    int wl = e % 28;
                    int t2 = e / 28;
                    int rr = t2 & 7;
                    int ci = t2 >> 3;
                    uint32_t dst = bs_base +
                        4u * ((rr * 28 + wl) * BS_STRIDE + kperm(ci));
                    cpa4(dst, xp + (((size_t)ci * PADW + dz) * PADW + hz + rr)
                                  * PADW + w0 + wl);
                }
                asm volatile("cp.async.commit_group;" ::: "memory");
                asm volatile("cp.async.wait_group 0;" ::: "memory");
            }
            __syncthreads();

            const int clo = (s2 >= 4) ? 1 : 0;
            const int chi = (s2 >= 4) ? 3 : 4;
            for (int c = clo; c <= chi; ++c) {
                const int tap = (a * 5 + b) * 5 + c;
                const float4* At = (const float4*)g_frag
                                 + ((size_t)tap * 16 * 8 + mw * 4) * 32 + lane;
                const float* Bp = Bs + c * BS_STRIDE + 2 * t4;
#pragma unroll 4
                for (int kb = 0; kb < 16; ++kb) {
                    float4 af[4];
                    const float4* Ak = At + kb * 256;   // 8 mt * 32 lanes
#pragma unroll
                    for (int i = 0; i < 4; ++i)
                        af[i] = __ldg(Ak + i * 32);
                    uint32_t bf[4][2];
#pragma unroll
                    for (int j = 0; j < 4; ++j) {
                        float2 v = *(const float2*)(Bp + spatj[j] * BS_STRIDE
                                                       + kb * 8);
                        bf[j][0] = __float_as_uint(v.x);
                        bf[j][1] = __float_as_uint(v.y);
                    }
#pragma unroll
                    for (int i = 0; i < 4; ++i)
#pragma unroll
                        for (int j = 0; j < 4; ++j)
                            mma8(acc[i][j], (const uint32_t*)&af[i], bf[j]);
                }
            }
        }
    }

    // epilogue: fragment -> float2 global stores
#pragma unroll
    for (int i = 0; i < 4; ++i) {
        const int o = mw * 64 + i * 16 + g;
#pragma unroll
        for (int j = 0; j < 4; ++j) {
            const int nl = nw * 32 + j * 8 + 2 * t4;
            const int hh = h0 + nl / 24;
            const int ww = w0 + nl % 24;
            float2 v0 = make_float2(acc[i][j][0], acc[i][j][1]);
            float2 v1 = make_float2(acc[i][j][2], acc[i][j][3]);
            *(float2*)(out + (((size_t)o * 48 + d) * 48 + hh) * 48 + ww) = v0;
            *(float2*)(out + (((size_t)(o + 8) * 48 + d) * 48 + hh) * 48 + ww) = v1;
        }
    }
}

// ---------------------------------------------------------------------------
extern "C" void kernel_launch(void* const* d_in, const int* in_sizes, int n_in,
                              void* d_out, int out_size) {
    const float* x    = (const float*)d_in[0];
    const float* wt   = (const float*)d_in[1];
    const float* scws = (const float*)d_in[2];
    const float* scwv = (const float*)d_in[3];
    float* out = (float*)d_out;

    const int N4 = 128 * PADW * PADW * 13;
    pad_k<<<(N4 + 255) / 256, 256>>>(x);
    build_k<<<125, 256>>>(wt, scws, scwv);

    const int smem_bytes = BS_FLOATS * 4;   // 123,648 B
    cudaFuncSetAttribute(conv_k, cudaFuncAttributeMaxDynamicSharedMemorySize,
                         smem_bytes);
    dim3 grid(2, 6, 48);   // w-tiles x h-tiles x d
    conv_k<<<grid, 384, smem_bytes>>>(out);
}

// round 8
// speedup vs baseline: 12.6575x; 2.6172x over previous
#include <cuda_runtime.h>
#include <cuda_fp16.h>
#include <math.h>
#include <stdint.h>

// ===========================================================================
// VoxelConvolution via mma.sync m16n8k16 FP16 (fp32 accum) implicit GEMM.
//   pad_k   : x -> xp transposed [dz][hz][wz][perm(ci)] fp16 (zero-padded)
//   build_k : weights -> g_frag[tap][kb16][mt][lane][4regs][2] fp16 fragments
//   conv_k  : CTA tile M=128 x N=192 (8h x 24w); double-buffered B slab per
//             (a,b) plane (cp.async 16B rows); A via LDG.128 fragments (L1).
// fp16 has the same 11-bit significand as tf32 -> rel_err ~3e-4 unchanged.
// ===========================================================================

#define PADW 52
__device__ __half xp[PADW * PADW * PADW * 128];   // 36 MB transposed fp16 input
__device__ __half g_frag[125 * 16384];            // 4 MB A fragments

// within-16 k permutation: storage pos for k=r is 4*((r&7)>>1)+2*((r>>3)&1)+(r&1)
// -> positions 4q..4q+3 hold k = {2q, 2q+1, 2q+8, 2q+9}  (one LDS.64 per B frag)
__device__ __forceinline__ int inv_pos16(int pos) {      // pos -> k
    int p4 = pos & 15;
    return (pos & ~15) | (2 * (p4 >> 2) + 8 * ((p4 >> 1) & 1) + (p4 & 1));
}
// A fragment half-index within a tap (16384 halfs):
// [kb 8][mt 8][lane 32][reg 4][half 2]
__device__ __forceinline__ int frag_off16(int o, int ci) {
    int kb   = ci >> 4;
    int lane = (o & 7) * 4 + ((ci & 7) >> 1);
    int reg  = ((ci >> 3) & 1) * 2 + ((o >> 3) & 1);
    int mt   = o >> 4;
    return (((kb * 8 + mt) * 32 + lane) * 4 + reg) * 2 + (ci & 1);
}

__device__ __forceinline__ void mma16(float* c, const uint4& a, const uint32_t* b) {
    asm volatile(
        "mma.sync.aligned.m16n8k16.row.col.f32.f16.f16.f32 "
        "{%0,%1,%2,%3}, {%4,%5,%6,%7}, {%8,%9}, {%0,%1,%2,%3};"
        : "+f"(c[0]), "+f"(c[1]), "+f"(c[2]), "+f"(c[3])
        : "r"(a.x), "r"(a.y), "r"(a.z), "r"(a.w), "r"(b[0]), "r"(b[1]));
}
__device__ __forceinline__ uint32_t smem_u32(const void* p) {
    uint32_t a;
    asm("{ .reg .u64 t; cvta.to.shared.u64 t, %1; cvt.u32.u64 %0, t; }" : "=r"(a) : "l"(p));
    return a;
}

// ---------------------------------------------------------------------------
// pad_k: xp[((dz*52+hz)*52+wz)*128 + pos] = fp16(x[inv(pos)][dz-2][hz-2][wz-2])
// ---------------------------------------------------------------------------
__global__ void pad_k(const float* __restrict__ x) {
    int idx = blockIdx.x * 256 + threadIdx.x;
    const int NT = PADW * PADW * PADW * 128;
    if (idx >= NT) return;
    int pos = idx & 127, vox = idx >> 7;
    int wz = vox % PADW;
    int t = vox / PADW;
    int hz = t % PADW;
    int dz = t / PADW;
    int ci = inv_pos16(pos);
    __half v = __float2half_rn(0.f);
    if (wz >= 2 && wz < 50 && hz >= 2 && hz < 50 && dz >= 2 && dz < 50)
        v = __float2half_rn(x[(((size_t)ci * 48 + dz - 2) * 48 + hz - 2) * 48 + wz - 2]);
    xp[idx] = v;
}

// ---------------------------------------------------------------------------
__global__ void build_k(const float* __restrict__ weight,   // [8][4096]
                        const float* __restrict__ scws,     // [32][32]
                        const float* __restrict__ scwv) {   // [32][32]
    int t = blockIdx.x;            // 0..124
    int a = t / 25, b = (t / 5) % 5, c = t % 5;

    __shared__ float emb_s[8];
    __shared__ float shv_s[3];
    if (threadIdx.x == 0) {
        double dx = a - 2, dy = b - 2, dz = c - 2;
        double d = sqrt(dx * dx + dy * dy + dz * dz);
        double step = 2.5 / 9.0;
        const double SMOOTH_C = 1.14136 * exp(2.0);
        for (int rb = 0; rb < 8; ++rb) {
            double val = (rb + 1) * step;
            double diff = (d - val) / step;
            double f = 0.0;
            if (fabs(diff) < 1.0) {
                double dc = diff;
                if (dc < -1.0 + 1e-6) dc = -1.0 + 1e-6;
                if (dc >  1.0 - 1e-6) dc =  1.0 - 1e-6;
                f = SMOOTH_C * exp(-1.0 / (1.0 + dc)) * exp(-1.0 / (1.0 - dc));
            }
            emb_s[rb] = (float)f;
        }
        double nn = d > 1e-12 ? d : 1e-12;
        const double SQ3 = 1.7320508075688772;
        shv_s[0] = (float)(SQ3 * dx / nn);
        shv_s[1] = (float)(SQ3 * dy / nn);
        shv_s[2] = (float)(SQ3 * dz / nn);
    }
    __syncthreads();

    const float PW0  = 0.125f;
    const float PW1  = 0.21650635094610965f;
    const float SQ3f = 1.7320508075688772f;
    const float INV  = 0.17677669529663687f;
    const float INV_NVOX = 1.0f / 81.0f;

    __half* A = g_frag + (size_t)t * 16384;

    for (int p = threadIdx.x; p < 1024; p += blockDim.x) {
        int u  = p >> 5;   // input mul
        int wm = p & 31;   // output mul
        float W[4];
#pragma unroll
        for (int cc = 0; cc < 4; ++cc) {
            float s = 0.f;
#pragma unroll
            for (int rb = 0; rb < 8; ++rb)
                s += emb_s[rb] * weight[rb * 4096 + cc * 1024 + u * 32 + wm];
            W[cc] = s * INV_NVOX;
        }
        float ksv = (PW0 / SQ3f) * W[3];
        float kvs = (PW1 / SQ3f) * W[1];
        float kvv = (PW1 / SQ3f) * W[2];

        {   // scalar->scalar (o=wm, ci=u) + center self-connection
            float v = PW0 * W[0];
            if (t == 62) v += INV * scws[u * 32 + wm] * INV_NVOX;
            A[frag_off16(wm, u)] = __float2half_rn(v);
        }
#pragma unroll
        for (int i = 0; i < 3; ++i)       // vector-in -> scalar-out
            A[frag_off16(wm, 32 + u * 3 + i)] = __float2half_rn(ksv * shv_s[i]);
#pragma unroll
        for (int k = 0; k < 3; ++k)       // scalar-in -> vector-out
            A[frag_off16(32 + wm * 3 + k, u)] = __float2half_rn(kvs * shv_s[k]);
#pragma unroll
        for (int i = 0; i < 3; ++i)       // vector-in -> vector-out (diag)
#pragma unroll
            for (int k = 0; k < 3; ++k) {
                float v = (i == k) ? kvv : 0.f;
                if (t == 62 && i == k) v += INV * scwv[u * 32 + wm] * INV_NVOX;
                A[frag_off16(32 + wm * 3 + k, 32 + u * 3 + i)] = __float2half_rn(v);
            }
    }
}

// ---------------------------------------------------------------------------
// conv_k: 384 threads (12 warps = 2 mhalf x 6 nblock), tile 128o x (8h x 24w).
// SMEM: 2 x B slab [224 rows][144 halfs]  (2 x 64,512 B = 129,024 B).
// ---------------------------------------------------------------------------
#define BS_H      144                    // halfs per smem row (288 B)
#define BS_ROWS   224
#define BUF_HALFS (BS_ROWS * BS_H)
#define BUF_BYTES (BUF_HALFS * 2)

// 21 valid (a,b) planes; c-range: s2<=2 -> [0,4], else [1,3]
__device__ const signed char PA[21] = {0,0,0, 1,1,1,1,1, 2,2,2,2,2, 3,3,3,3,3, 4,4,4};
__device__ const signed char PB[21] = {1,2,3, 0,1,2,3,4, 0,1,2,3,4, 0,1,2,3,4, 1,2,3};

__device__ __forceinline__ void stage_plane(uint32_t base, int dz, int hz,
                                            int w0, int tid) {
    for (int e = tid; e < BS_ROWS * 16; e += 384) {
        int row = e >> 4, ch = e & 15;
        int rr = row / 28, wl = row % 28;
        const __half* src = xp + ((((size_t)dz * PADW + hz + rr) * PADW) + w0 + wl) * 128
                          + ch * 8;
        uint32_t dst = base + row * (BS_H * 2) + ch * 16;
        asm volatile("cp.async.cg.shared.global [%0], [%1], 16;"
                     :: "r"(dst), "l"(src) : "memory");
    }
}

__global__ void __launch_bounds__(384, 1) conv_k(float* __restrict__ out) {
    extern __shared__ __align__(16) __half smh[];
    const uint32_t smbase = smem_u32(smh);

    const int tid  = threadIdx.x;
    const int lane = tid & 31;
    const int g    = lane >> 2;
    const int t4   = lane & 3;
    const int warp = tid >> 5;
    const int mw   = warp & 1;          // m half (64)
    const int nw   = warp >> 1;         // n block (32), 0..5
    const int w0   = blockIdx.x * 24;
    const int h0   = blockIdx.y * 8;
    const int d    = blockIdx.z;

    float acc[4][4][4];
#pragma unroll
    for (int i = 0; i < 4; ++i)
#pragma unroll
        for (int j = 0; j < 4; ++j)
#pragma unroll
            for (int q = 0; q < 4; ++q) acc[i][j][q] = 0.f;

    int spatj[4];
#pragma unroll
    for (int j = 0; j < 4; ++j) {
        int nl = nw * 32 + j * 8 + g;   // B frag col = groupID
        spatj[j] = (nl / 24) * 28 + (nl % 24);
    }

    // prologue: stage plane 0 into buf 0
    stage_plane(smbase, d + PA[0], h0 + PB[0], w0, tid);
    asm volatile("cp.async.commit_group;" ::: "memory");

    for (int p = 0; p < 21; ++p) {
        __syncthreads();                     // prev compute on buf[(p+1)&1] done
        if (p + 1 < 21) {
            stage_plane(smbase + ((p + 1) & 1) * BUF_BYTES,
                        d + PA[p + 1], h0 + PB[p + 1], w0, tid);
            asm volatile("cp.async.commit_group;" ::: "memory");
            asm volatile("cp.async.wait_group 1;" ::: "memory");
        } else {
            asm volatile("cp.async.wait_group 0;" ::: "memory");
        }
        __syncthreads();                     // plane p visible to all

        const int a  = PA[p], b = PB[p];
        const int s2 = (a - 2) * (a - 2) + (b - 2) * (b - 2);
        const int clo = (s2 >= 4) ? 1 : 0;
        const int chi = (s2 >= 4) ? 3 : 4;
        const __half* Bbuf = smh + (p & 1) * BUF_HALFS;

        for (int c = clo; c <= chi; ++c) {
            const int tap = (a * 5 + b) * 5 + c;
            const uint4* At = (const uint4*)g_frag + (size_t)tap * 2048
                            + mw * 128 + lane;
            const __half* Bp = Bbuf + c * BS_H + 4 * t4;
#pragma unroll 4
            for (int kb = 0; kb < 8; ++kb) {
                uint4 af[4];
                const uint4* Ak = At + kb * 256;
#pragma unroll
                for (int i = 0; i < 4; ++i)
                    af[i] = __ldg(Ak + i * 32);
                uint32_t bf[4][2];
#pragma unroll
                for (int j = 0; j < 4; ++j) {
                    uint2 v = *(const uint2*)(Bp + spatj[j] * BS_H + kb * 16);
                    bf[j][0] = v.x;
                    bf[j][1] = v.y;
                }
#pragma unroll
                for (int i = 0; i < 4; ++i)
#pragma unroll
                    for (int j = 0; j < 4; ++j)
                        mma16(acc[i][j], af[i], bf[j]);
            }
        }
    }

    // epilogue: fragment -> float2 global stores
#pragma unroll
    for (int i = 0; i < 4; ++i) {
        const int o = mw * 64 + i * 16 + g;
#pragma unroll
        for (int j = 0; j < 4; ++j) {
            const int nl = nw * 32 + j * 8 + 2 * t4;
            const int hh = h0 + nl / 24;
            const int ww = w0 + nl % 24;
            float2 v0 = make_float2(acc[i][j][0], acc[i][j][1]);
            float2 v1 = make_float2(acc[i][j][2], acc[i][j][3]);
            *(float2*)(out + (((size_t)o * 48 + d) * 48 + hh) * 48 + ww) = v0;
            *(float2*)(out + (((size_t)(o + 8) * 48 + d) * 48 + hh) * 48 + ww) = v1;
        }
    }
}

// ---------------------------------------------------------------------------
extern "C" void kernel_launch(void* const* d_in, const int* in_sizes, int n_in,
                              void* d_out, int out_size) {
    const float* x    = (const float*)d_in[0];
    const float* wt   = (const float*)d_in[1];
    const float* scws = (const float*)d_in[2];
    const float* scwv = (const float*)d_in[3];
    float* out = (float*)d_out;

    const int NT = PADW * PADW * PADW * 128;
    pad_k<<<(NT + 255) / 256, 256>>>(x);
    build_k<<<125, 256>>>(wt, scws, scwv);

    const int smem_bytes = 2 * BUF_BYTES;   // 129,024 B
    cudaFuncSetAttribute(conv_k, cudaFuncAttributeMaxDynamicSharedMemorySize,
                         smem_bytes);
    dim3 grid(2, 6, 48);   // w-tiles x h-tiles x d
    conv_k<<<grid, 384, smem_bytes>>>(out);
}

// round 9
// speedup vs baseline: 14.1595x; 1.1187x over previous
#include <cuda_runtime.h>
#include <cuda_fp16.h>
#include <math.h>
#include <stdint.h>

// ===========================================================================
// VoxelConvolution via mma.sync m16n8k16 FP16 (fp32 accum) implicit GEMM.
//   pad_k   : x -> xp transposed [dz][hz][wz][perm(ci)] fp16, smem-transposed
//             (coalesced read AND write)
//   build_k : weights -> g_frag[tap][kb16][mt][lane][4regs][2] fp16 fragments
//   conv_k  : CTA tile M=128 x N=192 (8h x 24w); double-buffered B slab per
//             (a,b) plane (cp.async 16B rows); A via LDG.128 fragments (L1);
//             kb-level software pipeline on A and B fragments.
// ===========================================================================

#define PADW 52
__device__ __half xp[PADW * PADW * PADW * 128];   // 36 MB transposed fp16 input
__device__ __half g_frag[125 * 16384];            // 4 MB A fragments

// within-16 k permutation: storage pos for k is 4*((k&7)>>1)+2*((k>>3)&1)+(k&1)
// -> positions 4q..4q+3 hold k = {2q, 2q+1, 2q+8, 2q+9}  (one LDS.64 per B frag)
__device__ __forceinline__ int pos16(int ci) {           // k -> storage pos
    return (ci & ~15) | (4 * ((ci & 7) >> 1) + 2 * ((ci >> 3) & 1) + (ci & 1));
}
// A fragment half-index within a tap (16384 halfs):
// [kb 8][mt 8][lane 32][reg 4][half 2]
__device__ __forceinline__ int frag_off16(int o, int ci) {
    int kb   = ci >> 4;
    int lane = (o & 7) * 4 + ((ci & 7) >> 1);
    int reg  = ((ci >> 3) & 1) * 2 + ((o >> 3) & 1);
    int mt   = o >> 4;
    return (((kb * 8 + mt) * 32 + lane) * 4 + reg) * 2 + (ci & 1);
}

__device__ __forceinline__ void mma16(float* c, const uint4& a, const uint32_t* b) {
    asm volatile(
        "mma.sync.aligned.m16n8k16.row.col.f32.f16.f16.f32 "
        "{%0,%1,%2,%3}, {%4,%5,%6,%7}, {%8,%9}, {%0,%1,%2,%3};"
        : "+f"(c[0]), "+f"(c[1]), "+f"(c[2]), "+f"(c[3])
        : "r"(a.x), "r"(a.y), "r"(a.z), "r"(a.w), "r"(b[0]), "r"(b[1]));
}
__device__ __forceinline__ uint32_t smem_u32(const void* p) {
    uint32_t a;
    asm("{ .reg .u64 t; cvta.to.shared.u64 t, %1; cvt.u32.u64 %0, t; }" : "=r"(a) : "l"(p));
    return a;
}

// ---------------------------------------------------------------------------
// pad_k: one block per (dz, hz) plane. Interior planes transpose a 48x128
// tile through smem; boundary planes (and boundary wz rows) write zeros.
// xp voxel row = 128 halfs (256 B), written as coalesced 16B chunks.
// ---------------------------------------------------------------------------
#define TR_STRIDE 136   // halfs; 16B-aligned rows, read-out conflict-free
__global__ void __launch_bounds__(256) pad_k(const float* __restrict__ x) {
    const int dz = blockIdx.x, hz = blockIdx.y;
    const int tid = threadIdx.x;
    __half* dst = xp + ((size_t)dz * PADW + hz) * PADW * 128;

    if (dz < 2 || dz >= 50 || hz < 2 || hz >= 50) {
        // whole plane is padding: 52*128 halfs = 832 uint4
        uint4 z = make_uint4(0, 0, 0, 0);
        for (int i = tid; i < 832; i += 256) ((uint4*)dst)[i] = z;
        return;
    }

    __shared__ __half sm[48 * TR_STRIDE];
    const float* src = x + ((size_t)0 * 48 + dz - 2) * 48 * 48 + (size_t)(hz - 2) * 48;
    // load + convert: lane-consecutive wz -> coalesced global reads
    for (int idx = tid; idx < 128 * 48; idx += 256) {
        int ci = idx / 48, wz = idx % 48;
        float v = src[(size_t)ci * 48 * 48 * 48 + wz];
        sm[wz * TR_STRIDE + pos16(ci)] = __float2half_rn(v);
    }
    __syncthreads();
    // write out interior wz rows: 48 rows x 16 chunks of 16B, coalesced
    for (int e = tid; e < 48 * 16; e += 256) {
        int wz = e >> 4, ch = e & 15;
        *(uint4*)(dst + (wz + 2) * 128 + ch * 8) =
            *(const uint4*)(sm + wz * TR_STRIDE + ch * 8);
    }
    // zero boundary wz rows {0,1,50,51}: 4 * 16 chunks
    uint4 z = make_uint4(0, 0, 0, 0);
    for (int e = tid; e < 64; e += 256) {
        int r = e >> 4, ch = e & 15;
        int wz = (r < 2) ? r : 48 + r;
        *(uint4*)(dst + wz * 128 + ch * 8) = z;
    }
}

// ---------------------------------------------------------------------------
__global__ void build_k(const float* __restrict__ weight,   // [8][4096]
                        const float* __restrict__ scws,     // [32][32]
                        const float* __restrict__ scwv) {   // [32][32]
    int t = blockIdx.x;            // 0..124
    int a = t / 25, b = (t / 5) % 5, c = t % 5;

    __shared__ float emb_s[8];
    __shared__ float shv_s[3];
    if (threadIdx.x == 0) {
        double dx = a - 2, dy = b - 2, dz = c - 2;
        double d = sqrt(dx * dx + dy * dy + dz * dz);
        double step = 2.5 / 9.0;
        const double SMOOTH_C = 1.14136 * exp(2.0);
        for (int rb = 0; rb < 8; ++rb) {
            double val = (rb + 1) * step;
            double diff = (d - val) / step;
            double f = 0.0;
            if (fabs(diff) < 1.0) {
                double dc = diff;
                if (dc < -1.0 + 1e-6) dc = -1.0 + 1e-6;
                if (dc >  1.0 - 1e-6) dc =  1.0 - 1e-6;
                f = SMOOTH_C * exp(-1.0 / (1.0 + dc)) * exp(-1.0 / (1.0 - dc));
            }
            emb_s[rb] = (float)f;
        }
        double nn = d > 1e-12 ? d : 1e-12;
        const double SQ3 = 1.7320508075688772;
        shv_s[0] = (float)(SQ3 * dx / nn);
        shv_s[1] = (float)(SQ3 * dy / nn);
        shv_s[2] = (float)(SQ3 * dz / nn);
    }
    __syncthreads();

    const float PW0  = 0.125f;
    const float PW1  = 0.21650635094610965f;
    const float SQ3f = 1.7320508075688772f;
    const float INV  = 0.17677669529663687f;
    const float INV_NVOX = 1.0f / 81.0f;

    __half* A = g_frag + (size_t)t * 16384;

    for (int p = threadIdx.x; p < 1024; p += blockDim.x) {
        int u  = p >> 5;   // input mul
        int wm = p & 31;   // output mul
        float W[4];
#pragma unroll
        for (int cc = 0; cc < 4; ++cc) {
            float s = 0.f;
#pragma unroll
            for (int rb = 0; rb < 8; ++rb)
                s += emb_s[rb] * weight[rb * 4096 + cc * 1024 + u * 32 + wm];
            W[cc] = s * INV_NVOX;
        }
        float ksv = (PW0 / SQ3f) * W[3];
        float kvs = (PW1 / SQ3f) * W[1];
        float kvv = (PW1 / SQ3f) * W[2];

        {   // scalar->scalar (o=wm, ci=u) + center self-connection
            float v = PW0 * W[0];
            if (t == 62) v += INV * scws[u * 32 + wm] * INV_NVOX;
            A[frag_off16(wm, u)] = __float2half_rn(v);
        }
#pragma unroll
        for (int i = 0; i < 3; ++i)       // vector-in -> scalar-out
            A[frag_off16(wm, 32 + u * 3 + i)] = __float2half_rn(ksv * shv_s[i]);
#pragma unroll
        for (int k = 0; k < 3; ++k)       // scalar-in -> vector-out
            A[frag_off16(32 + wm * 3 + k, u)] = __float2half_rn(kvs * shv_s[k]);
#pragma unroll
        for (int i = 0; i < 3; ++i)       // vector-in -> vector-out (diag)
#pragma unroll
            for (int k = 0; k < 3; ++k) {
                float v = (i == k) ? kvv : 0.f;
                if (t == 62 && i == k) v += INV * scwv[u * 32 + wm] * INV_NVOX;
                A[frag_off16(32 + wm * 3 + k, 32 + u * 3 + i)] = __float2half_rn(v);
            }
    }
}

// ---------------------------------------------------------------------------
// conv_k: 384 threads (12 warps = 2 mhalf x 6 nblock), tile 128o x (8h x 24w).
// SMEM: 2 x B slab [224 rows][144 halfs]  (2 x 64,512 B = 129,024 B).
// kb loop software-pipelined: A (LDG.128) + B (LDS.64) fragments prefetched
// one kb ahead so loads have a full mma-iteration of latency cover.
// ---------------------------------------------------------------------------
#define BS_H      144                    // halfs per smem row (288 B)
#define BS_ROWS   224
#define BUF_HALFS (BS_ROWS * BS_H)
#define BUF_BYTES (BUF_HALFS * 2)

// 21 valid (a,b) planes; c-range: s2<=2 -> [0,4], else [1,3]
__device__ const signed char PA[21] = {0,0,0, 1,1,1,1,1, 2,2,2,2,2, 3,3,3,3,3, 4,4,4};
__device__ const signed char PB[21] = {1,2,3, 0,1,2,3,4, 0,1,2,3,4, 0,1,2,3,4, 1,2,3};

__device__ __forceinline__ void stage_plane(uint32_t base, int dz, int hz,
                                            int w0, int tid) {
    for (int e = tid; e < BS_ROWS * 16; e += 384) {
        int row = e >> 4, ch = e & 15;
        int rr = row / 28, wl = row % 28;
        const __half* src = xp + ((((size_t)dz * PADW + hz + rr) * PADW) + w0 + wl) * 128
                          + ch * 8;
        uint32_t dst = base + row * (BS_H * 2) + ch * 16;
        asm volatile("cp.async.cg.shared.global [%0], [%1], 16;"
                     :: "r"(dst), "l"(src) : "memory");
    }
}

__global__ void __launch_bounds__(384, 1) conv_k(float* __restrict__ out) {
    extern __shared__ __align__(16) __half smh[];
    const uint32_t smbase = smem_u32(smh);

    const int tid  = threadIdx.x;
    const int lane = tid & 31;
    const int g    = lane >> 2;
    const int t4   = lane & 3;
    const int warp = tid >> 5;
    const int mw   = warp & 1;          // m half (64)
    const int nw   = warp >> 1;         // n block (32), 0..5
    const int w0   = blockIdx.x * 24;
    const int h0   = blockIdx.y * 8;
    const int d    = blockIdx.z;

    float acc[4][4][4];
#pragma unroll
    for (int i = 0; i < 4; ++i)
#pragma unroll
        for (int j = 0; j < 4; ++j)
#pragma unroll
            for (int q = 0; q < 4; ++q) acc[i][j][q] = 0.f;

    int spatj[4];
#pragma unroll
    for (int j = 0; j < 4; ++j) {
        int nl = nw * 32 + j * 8 + g;   // B frag col = groupID
        spatj[j] = (nl / 24) * 28 + (nl % 24);
    }

    // prologue: stage plane 0 into buf 0
    stage_plane(smbase, d + PA[0], h0 + PB[0], w0, tid);
    asm volatile("cp.async.commit_group;" ::: "memory");

    for (int p = 0; p < 21; ++p) {
        __syncthreads();                     // prev compute on buf[(p+1)&1] done
        if (p + 1 < 21) {
            stage_plane(smbase + ((p + 1) & 1) * BUF_BYTES,
                        d + PA[p + 1], h0 + PB[p + 1], w0, tid);
            asm volatile("cp.async.commit_group;" ::: "memory");
            asm volatile("cp.async.wait_group 1;" ::: "memory");
        } else {
            asm volatile("cp.async.wait_group 0;" ::: "memory");
        }
        __syncthreads();                     // plane p visible to all

        const int a  = PA[p], b = PB[p];
        const int s2 = (a - 2) * (a - 2) + (b - 2) * (b - 2);
        const int clo = (s2 >= 4) ? 1 : 0;
        const int chi = (s2 >= 4) ? 3 : 4;
        const __half* Bbuf = smh + (p & 1) * BUF_HALFS;

        for (int c = clo; c <= chi; ++c) {
            const int tap = (a * 5 + b) * 5 + c;
            const uint4* At = (const uint4*)g_frag + (size_t)tap * 2048
                            + mw * 128 + lane;
            const __half* Bp = Bbuf + c * BS_H + 4 * t4;

            uint4 af[2][4];
            uint32_t bf[2][4][2];
            // preload kb = 0
#pragma unroll
            for (int i = 0; i < 4; ++i)
                af[0][i] = __ldg(At + i * 32);
#pragma unroll
            for (int j = 0; j < 4; ++j) {
                uint2 v = *(const uint2*)(Bp + spatj[j] * BS_H);
                bf[0][j][0] = v.x;
                bf[0][j][1] = v.y;
            }
#pragma unroll
            for (int kb = 0; kb < 8; ++kb) {
                const int cur = kb & 1, nxt = cur ^ 1;
                if (kb < 7) {
                    const uint4* Ak = At + (kb + 1) * 256;
#pragma unroll
                    for (int i = 0; i < 4; ++i)
                        af[nxt][i] = __ldg(Ak + i * 32);
#pragma unroll
                    for (int j = 0; j < 4; ++j) {
                        uint2 v = *(const uint2*)(Bp + spatj[j] * BS_H
                                                     + (kb + 1) * 16);
                        bf[nxt][j][0] = v.x;
                        bf[nxt][j][1] = v.y;
                    }
                }
#pragma unroll
                for (int i = 0; i < 4; ++i)
#pragma unroll
                    for (int j = 0; j < 4; ++j)
                        mma16(acc[i][j], af[cur][i], bf[cur][j]);
            }
        }
    }

    // epilogue: fragment -> float2 global stores
#pragma unroll
    for (int i = 0; i < 4; ++i) {
        const int o = mw * 64 + i * 16 + g;
#pragma unroll
        for (int j = 0; j < 4; ++j) {
            const int nl = nw * 32 + j * 8 + 2 * t4;
            const int hh = h0 + nl / 24;
            const int ww = w0 + nl % 24;
            float2 v0 = make_float2(acc[i][j][0], acc[i][j][1]);
            float2 v1 = make_float2(acc[i][j][2], acc[i][j][3]);
            *(float2*)(out + (((size_t)o * 48 + d) * 48 + hh) * 48 + ww) = v0;
            *(float2*)(out + (((size_t)(o + 8) * 48 + d) * 48 + hh) * 48 + ww) = v1;
        }
    }
}

// ---------------------------------------------------------------------------
extern "C" void kernel_launch(void* const* d_in, const int* in_sizes, int n_in,
                              void* d_out, int out_size) {
    const float* x    = (const float*)d_in[0];
    const float* wt   = (const float*)d_in[1];
    const float* scws = (const float*)d_in[2];
    const float* scwv = (const float*)d_in[3];
    float* out = (float*)d_out;

    dim3 pgrid(PADW, PADW);
    pad_k<<<pgrid, 256>>>(x);
    build_k<<<125, 256>>>(wt, scws, scwv);

    const int smem_bytes = 2 * BUF_BYTES;   // 129,024 B
    cudaFuncSetAttribute(conv_k, cudaFuncAttributeMaxDynamicSharedMemorySize,
                         smem_bytes);
    dim3 grid(2, 6, 48);   // w-tiles x h-tiles x d
    conv_k<<<grid, 384, smem_bytes>>>(out);
}